// round 13
// baseline (speedup 1.0000x reference)
#include <cuda_runtime.h>
#include <cuda_bf16.h>
#include <cstdint>

// bf16 hi/lo split buffers
__device__ __nv_bfloat16 g_Qh[2048 * 1024], g_Ql[2048 * 1024];
__device__ __nv_bfloat16 g_Kh[2048 * 1024], g_Kl[2048 * 1024];
__device__ __nv_bfloat16 g_Vh[2048 * 1024], g_Vl[2048 * 1024];
__device__ __nv_bfloat16 g_VTh[1024 * 2048], g_VTl[1024 * 2048];  // V transposed [d][j]
__device__ __nv_bfloat16 g_Xh[2048 * 1024], g_Xl[2048 * 1024];
__device__ __nv_bfloat16 g_WTh[3 * 1024 * 1024], g_WTl[3 * 1024 * 1024];

// ---------------- helpers ----------------
__device__ __forceinline__ void mma16816(float* c, const uint32_t* a,
                                         uint32_t b0, uint32_t b1) {
    asm volatile(
        "mma.sync.aligned.m16n8k16.row.col.f32.bf16.bf16.f32 "
        "{%0,%1,%2,%3}, {%4,%5,%6,%7}, {%8,%9}, {%0,%1,%2,%3};"
        : "+f"(c[0]), "+f"(c[1]), "+f"(c[2]), "+f"(c[3])
        : "r"(a[0]), "r"(a[1]), "r"(a[2]), "r"(a[3]), "r"(b0), "r"(b1));
}
__device__ __forceinline__ void split2u(float x, float y, uint32_t& h, uint32_t& l) {
    __nv_bfloat162 hb = __float22bfloat162_rn(make_float2(x, y));
    h = *(uint32_t*)&hb;
    float xh = __uint_as_float(h << 16);
    float yh = __uint_as_float(h & 0xffff0000u);
    __nv_bfloat162 lb = __float22bfloat162_rn(make_float2(x - xh, y - yh));
    l = *(uint32_t*)&lb;
}
__device__ __forceinline__ uint32_t smem_addr_u32(const void* p) {
    uint32_t a;
    asm("{ .reg .u64 t; cvta.to.shared.u64 t, %1; cvt.u32.u64 %0, t; }" : "=r"(a) : "l"(p));
    return a;
}
__device__ __forceinline__ void ldsm4(uint32_t addr, uint32_t& r0, uint32_t& r1,
                                      uint32_t& r2, uint32_t& r3) {
    asm volatile("ldmatrix.sync.aligned.m8n8.x4.shared.b16 {%0,%1,%2,%3}, [%4];"
                 : "=r"(r0), "=r"(r1), "=r"(r2), "=r"(r3) : "r"(addr));
}
#define CP_ASYNC16(dst, src) \
    asm volatile("cp.async.cg.shared.global [%0], [%1], 16;" :: "r"(dst), "l"(src))
#define CP_COMMIT() asm volatile("cp.async.commit_group;")
#define CP_WAIT(n)  asm volatile("cp.async.wait_group %0;" :: "n"(n))

// ---------------------------------------------------------------------------
// Kernel 0a: X fp32 -> bf16 hi/lo
// ---------------------------------------------------------------------------
__global__ void convert_x_kernel(const float* __restrict__ X) {
    int row = blockIdx.x, col = threadIdx.x * 4;
    float4 v = *(const float4*)(X + (size_t)row * 1024 + col);
    uint32_t h0, l0, h1, l1;
    split2u(v.x, v.y, h0, l0); split2u(v.z, v.w, h1, l1);
    uint2 H = {h0, h1}, L = {l0, l1};
    *(uint2*)(g_Xh + (size_t)row * 1024 + col) = H;
    *(uint2*)(g_Xl + (size_t)row * 1024 + col) = L;
}

// ---------------------------------------------------------------------------
// Kernel 0b: W fp32 [k][n] -> transposed bf16 hi/lo [n][k]
// ---------------------------------------------------------------------------
__global__ void convert_w_kernel(const float* __restrict__ Wq,
                                 const float* __restrict__ Wk,
                                 const float* __restrict__ Wv) {
    __shared__ float t[32][33];
    const float* W = (blockIdx.z == 0) ? Wq : (blockIdx.z == 1) ? Wk : Wv;
    __nv_bfloat16* Th = g_WTh + (size_t)blockIdx.z * 1024 * 1024;
    __nv_bfloat16* Tl = g_WTl + (size_t)blockIdx.z * 1024 * 1024;
    int n0 = blockIdx.x * 32, k0 = blockIdx.y * 32;
    int tx = threadIdx.x, ty = threadIdx.y;
#pragma unroll
    for (int i = 0; i < 4; ++i)
        t[ty + 8 * i][tx] = W[(size_t)(k0 + ty + 8 * i) * 1024 + n0 + tx];
    __syncthreads();
#pragma unroll
    for (int i = 0; i < 4; ++i) {
        int n = n0 + ty + 8 * i;
        float v = t[tx][ty + 8 * i];
        __nv_bfloat16 hb = __float2bfloat16(v);
        __nv_bfloat16 lb = __float2bfloat16(v - __bfloat162float(hb));
        Th[(size_t)n * 1024 + k0 + tx] = hb;
        Tl[(size_t)n * 1024 + k0 + tx] = lb;
    }
}

// ---------------------------------------------------------------------------
// Kernel 0c: V bf16 [j][d] -> VT bf16 [d][j]
// ---------------------------------------------------------------------------
__global__ void transpose_v_kernel() {
    __shared__ __nv_bfloat16 t[32][33];
    const __nv_bfloat16* src = blockIdx.z ? g_Vl : g_Vh;
    __nv_bfloat16* dst = blockIdx.z ? g_VTl : g_VTh;
    int j0 = blockIdx.x * 32, d0 = blockIdx.y * 32;
    int tx = threadIdx.x, ty = threadIdx.y;
#pragma unroll
    for (int i = 0; i < 4; ++i)
        t[ty + 8 * i][tx] = src[(size_t)(j0 + ty + 8 * i) * 1024 + d0 + tx];
    __syncthreads();
#pragma unroll
    for (int i = 0; i < 4; ++i)
        dst[(size_t)(d0 + ty + 8 * i) * 2048 + j0 + tx] = t[tx][ty + 8 * i];
}

// ---------------------------------------------------------------------------
// Kernel 1: HMMA QKV GEMM (unchanged — protect the win)
// ---------------------------------------------------------------------------
#define G_STRIDE 80
#define G_ARR    10240
#define G_STAGE  40960
#define GEMM_SMEM 81920

__global__ __launch_bounds__(256, 2)
void qkv_hmma_kernel(const float* __restrict__ bq,
                     const float* __restrict__ bk,
                     const float* __restrict__ bv)
{
    extern __shared__ __align__(16) char smG[];
    const int z = blockIdx.z;
    const __nv_bfloat16* Bh = g_WTh + (size_t)z * 1024 * 1024;
    const __nv_bfloat16* Bl = g_WTl + (size_t)z * 1024 * 1024;
    const float* bias = (z == 0) ? bq : (z == 1) ? bk : bv;
    __nv_bfloat16* Gh = (z == 0) ? g_Qh : (z == 1) ? g_Kh : g_Vh;
    __nv_bfloat16* Gl = (z == 0) ? g_Ql : (z == 1) ? g_Kl : g_Vl;

    const int tid = threadIdx.x;
    const int warp = tid >> 5, lane = tid & 31;
    const int q = lane >> 2, r = lane & 3;
    const int wm = warp & 3, wn = warp >> 2;
    const int m0 = blockIdx.y * 128, n0 = blockIdx.x * 128;

    float c[2][8][4];
#pragma unroll
    for (int mf = 0; mf < 2; ++mf)
#pragma unroll
        for (int nc = 0; nc < 8; ++nc)
#pragma unroll
            for (int i = 0; i < 4; ++i) c[mf][nc][i] = 0.f;

    auto stage = [&](int buf, int k0) {
        char* base = smG + buf * G_STAGE;
#pragma unroll
        for (int l = tid; l < 2048; l += 256) {
            int arr = l >> 9, idx = l & 511;
            int rr = idx >> 2, ch = idx & 3;
            const __nv_bfloat16* src;
            size_t off;
            if (arr < 2) {
                src = (arr == 0) ? g_Xh : g_Xl;
                off = (size_t)(m0 + rr) * 1024 + k0 + ch * 8;
            } else {
                src = (arr == 2) ? Bh : Bl;
                off = (size_t)(n0 + rr) * 1024 + k0 + ch * 8;
            }
            uint32_t dst = smem_addr_u32(base + arr * G_ARR + rr * G_STRIDE + ch * 16);
            CP_ASYNC16(dst, src + off);
        }
    };

    stage(0, 0);
    CP_COMMIT();

    for (int kt = 0; kt < 32; ++kt) {
        if (kt + 1 < 32) {
            stage((kt + 1) & 1, (kt + 1) * 32);
            CP_COMMIT();
            CP_WAIT(1);
        } else {
            CP_WAIT(0);
        }
        __syncthreads();

        char* base = smG + (kt & 1) * G_STAGE;
        char* Ah = base;
        char* Al = base + G_ARR;
        char* Bsh = base + 2 * G_ARR;
        char* Bsl = base + 3 * G_ARR;

#pragma unroll
        for (int k16 = 0; k16 < 2; ++k16) {
            const int kb = k16 * 32 + r * 4;
            uint32_t ah[2][4], al[2][4];
#pragma unroll
            for (int mf = 0; mf < 2; ++mf) {
                int mrow = wm * 32 + mf * 16 + q;
                ah[mf][0] = *(uint32_t*)(Ah + mrow * G_STRIDE + kb);
                ah[mf][1] = *(uint32_t*)(Ah + (mrow + 8) * G_STRIDE + kb);
                ah[mf][2] = *(uint32_t*)(Ah + mrow * G_STRIDE + kb + 16);
                ah[mf][3] = *(uint32_t*)(Ah + (mrow + 8) * G_STRIDE + kb + 16);
                al[mf][0] = *(uint32_t*)(Al + mrow * G_STRIDE + kb);
                al[mf][1] = *(uint32_t*)(Al + (mrow + 8) * G_STRIDE + kb);
                al[mf][2] = *(uint32_t*)(Al + mrow * G_STRIDE + kb + 16);
                al[mf][3] = *(uint32_t*)(Al + (mrow + 8) * G_STRIDE + kb + 16);
            }
#pragma unroll
            for (int nc = 0; nc < 8; ++nc) {
                int nrow = wn * 64 + nc * 8 + q;
                uint32_t bh0 = *(uint32_t*)(Bsh + nrow * G_STRIDE + kb);
                uint32_t bh1 = *(uint32_t*)(Bsh + nrow * G_STRIDE + kb + 16);
                uint32_t bl0 = *(uint32_t*)(Bsl + nrow * G_STRIDE + kb);
                uint32_t bl1 = *(uint32_t*)(Bsl + nrow * G_STRIDE + kb + 16);
#pragma unroll
                for (int mf = 0; mf < 2; ++mf) {
                    mma16816(c[mf][nc], ah[mf], bh0, bh1);
                    mma16816(c[mf][nc], ah[mf], bl0, bl1);
                    mma16816(c[mf][nc], al[mf], bh0, bh1);
                }
            }
        }
        __syncthreads();
    }

#pragma unroll
    for (int mf = 0; mf < 2; ++mf) {
        int row = m0 + wm * 32 + mf * 16 + q;
#pragma unroll
        for (int nc = 0; nc < 8; ++nc) {
            int col = n0 + wn * 64 + nc * 8 + r * 2;
            float b0 = bias[col], b1 = bias[col + 1];
            uint32_t h, l;
            split2u(c[mf][nc][0] + b0, c[mf][nc][1] + b1, h, l);
            *(uint32_t*)(Gh + (size_t)row * 1024 + col) = h;
            *(uint32_t*)(Gl + (size_t)row * 1024 + col) = l;
            split2u(c[mf][nc][2] + b0, c[mf][nc][3] + b1, h, l);
            *(uint32_t*)(Gh + (size_t)(row + 8) * 1024 + col) = h;
            *(uint32_t*)(Gl + (size_t)(row + 8) * 1024 + col) = l;
        }
    }
}

// ---------------------------------------------------------------------------
// Kernel 2: HMMA flash attention (R10 structure; S uses 2-term split:
// qh*kh + qh*kl — ql term dropped, error budget ~1e-4 << 1e-3)
// ---------------------------------------------------------------------------
#define OFF_KH   0
#define OFF_KL   9216
#define OFF_VTH  18432
#define OFF_VTL  27648
#define OFF_AK   36864
#define OFF_BAND 70656
#define OFF_MS   105472
#define ATT_SMEM 105728
#define OFF_WRVT OFF_KH

__global__ __launch_bounds__(256, 2)
void attn_mma_kernel(const float* __restrict__ mask,
                     const float* __restrict__ Wrk,   // [64][129]
                     const float* __restrict__ Wrv,   // [129][64]
                     float* __restrict__ out)
{
    extern __shared__ __align__(16) char sm[];
    const int tid  = threadIdx.x;
    const int warp = tid >> 5, lane = tid & 31;
    const int tq = lane >> 2, tr = lane & 3;
    const int lr = warp * 16 + tq;
    const int i0 = blockIdx.x * 128, hc = blockIdx.y * 64;

    __nv_bfloat16* AK = (__nv_bfloat16*)(sm + OFF_AK);
    float* MS = (float*)(sm + OFF_MS);
    const uint32_t sb = smem_addr_u32(sm);
    const uint32_t loff = ((lane & 7) + ((lane >> 1) & 8)) * 144 + ((lane & 8) << 1);
    const uint32_t loff272 = ((lane & 7) + ((lane >> 1) & 8)) * 272 + ((lane & 8) << 1);

    // ---- stage WrkT (hi) into KH/KL ----
    for (int l = tid; l < 1024; l += 256) {
        int w = l >> 4, dg = (l & 15) << 2;
        uint32_t a0, a1, b0, b1, t;
        split2u(Wrk[(dg + 0) * 129 + w],      Wrk[(dg + 1) * 129 + w],      a0, t);
        split2u(Wrk[(dg + 2) * 129 + w],      Wrk[(dg + 3) * 129 + w],      a1, t);
        split2u(Wrk[(dg + 0) * 129 + w + 64], Wrk[(dg + 1) * 129 + w + 64], b0, t);
        split2u(Wrk[(dg + 2) * 129 + w + 64], Wrk[(dg + 3) * 129 + w + 64], b1, t);
        uint2 A = {a0, a1}, B = {b0, b1};
        *(uint2*)(sm + OFF_KH + w * 144 + dg * 2) = A;
        *(uint2*)(sm + OFF_KL + w * 144 + dg * 2) = B;
    }
    for (int l = tid; l < 8704; l += 256) ((uint32_t*)(sm + OFF_BAND))[l] = 0;
    if (tid < 128) {
        float s = 0.f;
        const __nv_bfloat16* qh_ = g_Qh + (size_t)(i0 + tid) * 1024 + hc;
        const __nv_bfloat16* ql_ = g_Ql + (size_t)(i0 + tid) * 1024 + hc;
#pragma unroll 8
        for (int d = 0; d < 64; ++d) {
            float qv = __bfloat162float(qh_[d]) + __bfloat162float(ql_[d]);
            s += qv * Wrk[d * 129 + 128];
        }
        AK[tid * 132 + 128] = __float2bfloat16(s);
    }
    __syncthreads();

    // ---- Q hi fragments only (ql term dropped from S) ----
    uint32_t qh[4][4];
#pragma unroll
    for (int kc = 0; kc < 4; ++kc) {
        size_t r0 = (size_t)(i0 + lr) * 1024 + hc + kc * 16 + tr * 2;
        size_t r1 = (size_t)(i0 + lr + 8) * 1024 + hc + kc * 16 + tr * 2;
        qh[kc][0] = *(const uint32_t*)(g_Qh + r0);
        qh[kc][1] = *(const uint32_t*)(g_Qh + r1);
        qh[kc][2] = *(const uint32_t*)(g_Qh + r0 + 8);
        qh[kc][3] = *(const uint32_t*)(g_Qh + r1 + 8);
    }

    // ---- ak = Q @ WrkT^T (hi) via ldmatrix ----
#pragma unroll
    for (int half = 0; half < 2; ++half) {
        const uint32_t KO = sb + (half ? OFF_KL : OFF_KH);
#pragma unroll
        for (int g = 0; g < 4; ++g) {
            float ca[4] = {0.f, 0.f, 0.f, 0.f}, cb[4] = {0.f, 0.f, 0.f, 0.f};
#pragma unroll
            for (int kc = 0; kc < 4; ++kc) {
                uint32_t h0, h1, h2, h3;
                ldsm4(KO + g * 2304 + kc * 32 + loff, h0, h1, h2, h3);
                mma16816(ca, qh[kc], h0, h1);
                mma16816(cb, qh[kc], h2, h3);
            }
#pragma unroll
            for (int pp = 0; pp < 2; ++pp) {
                const float* cc = pp ? cb : ca;
                int w = half * 64 + (2 * g + pp) * 8 + tr * 2;
                AK[lr * 132 + w]           = __float2bfloat16(cc[0]);
                AK[lr * 132 + w + 1]       = __float2bfloat16(cc[1]);
                AK[(lr + 8) * 132 + w]     = __float2bfloat16(cc[2]);
                AK[(lr + 8) * 132 + w + 1] = __float2bfloat16(cc[3]);
            }
        }
    }
    __syncthreads();   // KH/KL dead -> safe for cp.async overwrite

    // ---- pipelined staging lambdas ----
    auto stageK = [&](int j0) {
#pragma unroll
        for (int l = tid; l < 1024; l += 256) {
            int arr = l >> 9, idx = l & 511;
            int r = idx >> 3, ch = idx & 7;
            const __nv_bfloat16* src =
                (arr ? g_Kl : g_Kh) + (size_t)(j0 + r) * 1024 + hc + ch * 8;
            uint32_t dst = smem_addr_u32(sm + (arr ? OFF_KL : OFF_KH) + r * 144 + ch * 16);
            CP_ASYNC16(dst, src);
        }
        if (tid < 16) {
            uint32_t dst = smem_addr_u32(sm + OFF_MS + tid * 16);
            CP_ASYNC16(dst, mask + j0 + tid * 4);
        }
    };
    auto stageV = [&](int j0) {
#pragma unroll
        for (int l = tid; l < 1024; l += 256) {
            int arr = l >> 9, idx = l & 511;
            int d = idx >> 3, ch = idx & 7;
            const __nv_bfloat16* src =
                (arr ? g_VTl : g_VTh) + (size_t)(hc + d) * 2048 + j0 + ch * 8;
            uint32_t dst = smem_addr_u32(sm + (arr ? OFF_VTL : OFF_VTH) + d * 144 + ch * 16);
            CP_ASYNC16(dst, src);
        }
    };

    stageK(0); CP_COMMIT();
    stageV(0); CP_COMMIT();

    float ctx[8][4];
#pragma unroll
    for (int nc = 0; nc < 8; ++nc)
#pragma unroll
        for (int qq = 0; qq < 4; ++qq) ctx[nc][qq] = 0.f;
    float rs0 = 0.f, rs1 = 0.f, pe0 = 0.f, pe1 = 0.f;

#pragma unroll 1
    for (int jt = 0; jt < 32; ++jt) {
        const int j0 = jt * 64;
        CP_WAIT(1);              // K(jt)+mask ready (V may be in flight)
        __syncthreads();

        // ---- S = Q K^T (2-term split: qh*kh + qh*kl) via ldmatrix ----
        float c[8][4];
#pragma unroll
        for (int nc = 0; nc < 8; ++nc)
#pragma unroll
            for (int qq = 0; qq < 4; ++qq) c[nc][qq] = 0.f;
#pragma unroll
        for (int kc = 0; kc < 4; ++kc) {
#pragma unroll
            for (int g = 0; g < 4; ++g) {
                uint32_t h0, h1, h2, h3, e0, e1, e2, e3;
                ldsm4(sb + OFF_KH + g * 2304 + kc * 32 + loff, h0, h1, h2, h3);
                ldsm4(sb + OFF_KL + g * 2304 + kc * 32 + loff, e0, e1, e2, e3);
                mma16816(c[2 * g],     qh[kc], h0, h1);
                mma16816(c[2 * g],     qh[kc], e0, e1);
                mma16816(c[2 * g + 1], qh[kc], h2, h3);
                mma16816(c[2 * g + 1], qh[kc], e2, e3);
            }
        }
        // snapshot additive mask before MS buffer gets overwritten by prefetch
        float am0[8], am1[8];
#pragma unroll
        for (int nc = 0; nc < 8; ++nc) {
            am0[nc] = (1.0f - MS[nc * 8 + tr * 2])     * (-1.0e30f);
            am1[nc] = (1.0f - MS[nc * 8 + tr * 2 + 1]) * (-1.0e30f);
        }
        __syncthreads();         // K + MS dead
        if (jt + 1 < 32) { stageK(j0 + 64); CP_COMMIT(); }

        // ---- epilogue: bias + scale + mask + exp2; band scatter ----
        const int sb0 = j0 - i0 + 64;
        const bool doBand = (sb0 >= -63 && sb0 <= 255);
#pragma unroll
        for (int nc = 0; nc < 8; ++nc) {
#pragma unroll
            for (int idx = 0; idx < 4; ++idx) {
                int lrr = lr + ((idx >> 1) << 3);
                int col = nc * 8 + tr * 2 + (idx & 1);
                float s = c[nc][idx];
                int w = sb0 + col - lrr;
                if (doBand && w >= 0 && w <= 128)
                    s += __bfloat162float(AK[lrr * 132 + w]);
                float am = (idx & 1) ? am1[nc] : am0[nc];
                float e = exp2f(fmaf(s, 0.18033688f, am));
                if (idx < 2) rs0 += e; else rs1 += e;
                if (doBand) {
                    if (w >= 0 && w < 128)
                        *(__nv_bfloat16*)(sm + OFF_BAND + lrr * 272 + w * 2) =
                            __float2bfloat16(e);
                    else if (w == 128) { if (idx < 2) pe0 = e; else pe1 = e; }
                }
                c[nc][idx] = e;
            }
        }

        // ---- repack P as A-fragments (hi/lo) ----
        uint32_t ph[4][4], pl[4][4];
#pragma unroll
        for (int kc = 0; kc < 4; ++kc) {
            split2u(c[2 * kc][0],     c[2 * kc][1],     ph[kc][0], pl[kc][0]);
            split2u(c[2 * kc][2],     c[2 * kc][3],     ph[kc][1], pl[kc][1]);
            split2u(c[2 * kc + 1][0], c[2 * kc + 1][1], ph[kc][2], pl[kc][2]);
            split2u(c[2 * kc + 1][2], c[2 * kc + 1][3], ph[kc][3], pl[kc][3]);
        }

        if (jt + 1 < 32) { CP_WAIT(1); } else { CP_WAIT(0); }   // V(jt) ready
        __syncthreads();

        // ---- ctx += P V (3-term split) via ldmatrix ----
#pragma unroll
        for (int kc = 0; kc < 4; ++kc) {
#pragma unroll
            for (int g = 0; g < 4; ++g) {
                uint32_t h0, h1, h2, h3, e0, e1, e2, e3;
                ldsm4(sb + OFF_VTH + g * 2304 + kc * 32 + loff, h0, h1, h2, h3);
                ldsm4(sb + OFF_VTL + g * 2304 + kc * 32 + loff, e0, e1, e2, e3);
                mma16816(ctx[2 * g],     ph[kc], h0, h1);
                mma16816(ctx[2 * g],     ph[kc], e0, e1);
                mma16816(ctx[2 * g],     pl[kc], h0, h1);
                mma16816(ctx[2 * g + 1], ph[kc], h2, h3);
                mma16816(ctx[2 * g + 1], ph[kc], e2, e3);
                mma16816(ctx[2 * g + 1], pl[kc], h2, h3);
            }
        }
        __syncthreads();         // V dead
        if (jt + 1 < 32) { stageV(j0 + 64); CP_COMMIT(); }
    }

    // ---- stage WrvT [d][136] (hi only), overlay on K buffers ----
    for (int l = tid; l < 8192; l += 256) {
        int d = l >> 7, w = l & 127;
        *(__nv_bfloat16*)(sm + OFF_WRVT + d * 272 + w * 2) =
            __float2bfloat16(Wrv[w * 64 + d]);
    }
    __syncthreads();

    // ---- ctx += band @ WrvT^T (ldmatrix, 272B stride) ----
#pragma unroll
    for (int kc = 0; kc < 8; ++kc) {
        int cb = (kc * 16 + tr * 2) * 2;
        uint32_t af[4];
        af[0] = *(uint32_t*)(sm + OFF_BAND + lr * 272 + cb);
        af[1] = *(uint32_t*)(sm + OFF_BAND + (lr + 8) * 272 + cb);
        af[2] = *(uint32_t*)(sm + OFF_BAND + lr * 272 + cb + 16);
        af[3] = *(uint32_t*)(sm + OFF_BAND + (lr + 8) * 272 + cb + 16);
#pragma unroll
        for (int g = 0; g < 4; ++g) {
            uint32_t h0, h1, h2, h3;
            ldsm4(sb + OFF_WRVT + g * 16 * 272 + kc * 32 + loff272, h0, h1, h2, h3);
            mma16816(ctx[2 * g],     af, h0, h1);
            mma16816(ctx[2 * g + 1], af, h2, h3);
        }
    }

    // ---- reduce rowsums / edge-p across the quad, write out ----
    rs0 += __shfl_xor_sync(0xffffffffu, rs0, 1);
    rs0 += __shfl_xor_sync(0xffffffffu, rs0, 2);
    rs1 += __shfl_xor_sync(0xffffffffu, rs1, 1);
    rs1 += __shfl_xor_sync(0xffffffffu, rs1, 2);
    pe0 += __shfl_xor_sync(0xffffffffu, pe0, 1);
    pe0 += __shfl_xor_sync(0xffffffffu, pe0, 2);
    pe1 += __shfl_xor_sync(0xffffffffu, pe1, 1);
    pe1 += __shfl_xor_sync(0xffffffffu, pe1, 2);
    float inv0 = 1.0f / rs0, inv1 = 1.0f / rs1;
    const float* wrvE = Wrv + 128 * 64;
#pragma unroll
    for (int nc = 0; nc < 8; ++nc) {
        int d = nc * 8 + tr * 2;
        float2 o0, o1;
        o0.x = (ctx[nc][0] + pe0 * wrvE[d])     * inv0;
        o0.y = (ctx[nc][1] + pe0 * wrvE[d + 1]) * inv0;
        o1.x = (ctx[nc][2] + pe1 * wrvE[d])     * inv1;
        o1.y = (ctx[nc][3] + pe1 * wrvE[d + 1]) * inv1;
        *(float2*)(out + (size_t)(i0 + lr) * 1024 + hc + d)     = o0;
        *(float2*)(out + (size_t)(i0 + lr + 8) * 1024 + hc + d) = o1;
    }
}

// ---------------------------------------------------------------------------
extern "C" void kernel_launch(void* const* d_in, const int* in_sizes, int n_in,
                              void* d_out, int out_size)
{
    const float* X   = (const float*)d_in[0];
    const float* msk = (const float*)d_in[1];
    const float* Wq  = (const float*)d_in[2];
    const float* bq  = (const float*)d_in[3];
    const float* Wk  = (const float*)d_in[4];
    const float* bk  = (const float*)d_in[5];
    const float* Wv  = (const float*)d_in[6];
    const float* bv  = (const float*)d_in[7];
    const float* Wrk = (const float*)d_in[8];
    const float* Wrv = (const float*)d_in[9];
    float* out = (float*)d_out;

    cudaFuncSetAttribute(qkv_hmma_kernel,
                         cudaFuncAttributeMaxDynamicSharedMemorySize, GEMM_SMEM);
    cudaFuncSetAttribute(attn_mma_kernel,
                         cudaFuncAttributeMaxDynamicSharedMemorySize, ATT_SMEM);

    convert_x_kernel<<<2048, 256>>>(X);
    convert_w_kernel<<<dim3(32, 32, 3), dim3(32, 8)>>>(Wq, Wk, Wv);
    qkv_hmma_kernel<<<dim3(8, 16, 3), 256, GEMM_SMEM>>>(bq, bk, bv);
    transpose_v_kernel<<<dim3(64, 32, 2), dim3(32, 8)>>>();

    dim3 gAttn(16, 16);
    attn_mma_kernel<<<gAttn, 256, ATT_SMEM>>>(msk, Wrk, Wrv, out);
}

// round 17
// speedup vs baseline: 1.0820x; 1.0820x over previous
#include <cuda_runtime.h>
#include <cuda_bf16.h>
#include <cuda_fp16.h>
#include <cstdint>

// fp16 hi/lo split Q/K/V (written by QKV GEMM epilogue)
__device__ __half g_Qh[2048 * 1024], g_Ql[2048 * 1024];
__device__ __half g_Kh[2048 * 1024];
__device__ __half g_Vh[2048 * 1024], g_Vl[2048 * 1024];
__device__ __half g_VTh[1024 * 2048], g_VTl[1024 * 2048];  // V transposed [d][j]
// bf16 inputs for the QKV GEMM itself (3-term bf16 split, unchanged)
__device__ __nv_bfloat16 g_Xh[2048 * 1024], g_Xl[2048 * 1024];
__device__ __nv_bfloat16 g_WTh[3 * 1024 * 1024], g_WTl[3 * 1024 * 1024];

// ---------------- helpers ----------------
__device__ __forceinline__ void mma16816bf(float* c, const uint32_t* a,
                                           uint32_t b0, uint32_t b1) {
    asm volatile(
        "mma.sync.aligned.m16n8k16.row.col.f32.bf16.bf16.f32 "
        "{%0,%1,%2,%3}, {%4,%5,%6,%7}, {%8,%9}, {%0,%1,%2,%3};"
        : "+f"(c[0]), "+f"(c[1]), "+f"(c[2]), "+f"(c[3])
        : "r"(a[0]), "r"(a[1]), "r"(a[2]), "r"(a[3]), "r"(b0), "r"(b1));
}
__device__ __forceinline__ void mma16816h(float* c, const uint32_t* a,
                                          uint32_t b0, uint32_t b1) {
    asm volatile(
        "mma.sync.aligned.m16n8k16.row.col.f32.f16.f16.f32 "
        "{%0,%1,%2,%3}, {%4,%5,%6,%7}, {%8,%9}, {%0,%1,%2,%3};"
        : "+f"(c[0]), "+f"(c[1]), "+f"(c[2]), "+f"(c[3])
        : "r"(a[0]), "r"(a[1]), "r"(a[2]), "r"(a[3]), "r"(b0), "r"(b1));
}
// bf16 hi/lo packed split (GEMM input conversion)
__device__ __forceinline__ void split2u(float x, float y, uint32_t& h, uint32_t& l) {
    __nv_bfloat162 hb = __float22bfloat162_rn(make_float2(x, y));
    h = *(uint32_t*)&hb;
    float xh = __uint_as_float(h << 16);
    float yh = __uint_as_float(h & 0xffff0000u);
    __nv_bfloat162 lb = __float22bfloat162_rn(make_float2(x - xh, y - yh));
    l = *(uint32_t*)&lb;
}
// fp16 hi/lo packed split (attention datapath)
__device__ __forceinline__ void split2h(float x, float y, uint32_t& h, uint32_t& l) {
    __half2 hb = __floats2half2_rn(x, y);
    h = *(uint32_t*)&hb;
    float2 f = __half22float2(hb);
    __half2 lb = __floats2half2_rn(x - f.x, y - f.y);
    l = *(uint32_t*)&lb;
}
__device__ __forceinline__ uint32_t smem_addr_u32(const void* p) {
    uint32_t a;
    asm("{ .reg .u64 t; cvta.to.shared.u64 t, %1; cvt.u32.u64 %0, t; }" : "=r"(a) : "l"(p));
    return a;
}
__device__ __forceinline__ void ldsm4(uint32_t addr, uint32_t& r0, uint32_t& r1,
                                      uint32_t& r2, uint32_t& r3) {
    asm volatile("ldmatrix.sync.aligned.m8n8.x4.shared.b16 {%0,%1,%2,%3}, [%4];"
                 : "=r"(r0), "=r"(r1), "=r"(r2), "=r"(r3) : "r"(addr));
}
#define CP_ASYNC16(dst, src) \
    asm volatile("cp.async.cg.shared.global [%0], [%1], 16;" :: "r"(dst), "l"(src))
#define CP_COMMIT() asm volatile("cp.async.commit_group;")
#define CP_WAIT(n)  asm volatile("cp.async.wait_group %0;" :: "n"(n))

// ---------------------------------------------------------------------------
// Kernel 0a: X fp32 -> bf16 hi/lo (GEMM input)
// ---------------------------------------------------------------------------
__global__ void convert_x_kernel(const float* __restrict__ X) {
    int row = blockIdx.x, col = threadIdx.x * 4;
    float4 v = *(const float4*)(X + (size_t)row * 1024 + col);
    uint32_t h0, l0, h1, l1;
    split2u(v.x, v.y, h0, l0); split2u(v.z, v.w, h1, l1);
    uint2 H = {h0, h1}, L = {l0, l1};
    *(uint2*)(g_Xh + (size_t)row * 1024 + col) = H;
    *(uint2*)(g_Xl + (size_t)row * 1024 + col) = L;
}

// ---------------------------------------------------------------------------
// Kernel 0b: W fp32 [k][n] -> transposed bf16 hi/lo [n][k]
// ---------------------------------------------------------------------------
__global__ void convert_w_kernel(const float* __restrict__ Wq,
                                 const float* __restrict__ Wk,
                                 const float* __restrict__ Wv) {
    __shared__ float t[32][33];
    const float* W = (blockIdx.z == 0) ? Wq : (blockIdx.z == 1) ? Wk : Wv;
    __nv_bfloat16* Th = g_WTh + (size_t)blockIdx.z * 1024 * 1024;
    __nv_bfloat16* Tl = g_WTl + (size_t)blockIdx.z * 1024 * 1024;
    int n0 = blockIdx.x * 32, k0 = blockIdx.y * 32;
    int tx = threadIdx.x, ty = threadIdx.y;
#pragma unroll
    for (int i = 0; i < 4; ++i)
        t[ty + 8 * i][tx] = W[(size_t)(k0 + ty + 8 * i) * 1024 + n0 + tx];
    __syncthreads();
#pragma unroll
    for (int i = 0; i < 4; ++i) {
        int n = n0 + ty + 8 * i;
        float v = t[tx][ty + 8 * i];
        __nv_bfloat16 hb = __float2bfloat16(v);
        __nv_bfloat16 lb = __float2bfloat16(v - __bfloat162float(hb));
        Th[(size_t)n * 1024 + k0 + tx] = hb;
        Tl[(size_t)n * 1024 + k0 + tx] = lb;
    }
}

// ---------------------------------------------------------------------------
// Kernel 0c: V fp16 [j][d] -> VT fp16 [d][j]
// ---------------------------------------------------------------------------
__global__ void transpose_v_kernel() {
    __shared__ __half t[32][33];
    const __half* src = blockIdx.z ? g_Vl : g_Vh;
    __half* dst = blockIdx.z ? g_VTl : g_VTh;
    int j0 = blockIdx.x * 32, d0 = blockIdx.y * 32;
    int tx = threadIdx.x, ty = threadIdx.y;
#pragma unroll
    for (int i = 0; i < 4; ++i)
        t[ty + 8 * i][tx] = src[(size_t)(j0 + ty + 8 * i) * 1024 + d0 + tx];
    __syncthreads();
#pragma unroll
    for (int i = 0; i < 4; ++i)
        dst[(size_t)(d0 + ty + 8 * i) * 2048 + j0 + tx] = t[tx][ty + 8 * i];
}

// ---------------------------------------------------------------------------
// Kernel 1: HMMA QKV GEMM (bf16 3-term internals; epilogue emits fp16 hi/lo)
// ---------------------------------------------------------------------------
#define G_STRIDE 80
#define G_ARR    10240
#define G_STAGE  40960
#define GEMM_SMEM 81920

__global__ __launch_bounds__(256, 2)
void qkv_hmma_kernel(const float* __restrict__ bq,
                     const float* __restrict__ bk,
                     const float* __restrict__ bv)
{
    extern __shared__ __align__(16) char smG[];
    const int z = blockIdx.z;
    const __nv_bfloat16* Bh = g_WTh + (size_t)z * 1024 * 1024;
    const __nv_bfloat16* Bl = g_WTl + (size_t)z * 1024 * 1024;
    const float* bias = (z == 0) ? bq : (z == 1) ? bk : bv;
    __half* Gh = (z == 0) ? g_Qh : (z == 1) ? g_Kh : g_Vh;
    __half* Gl = (z == 0) ? g_Ql : (z == 1) ? (__half*)nullptr : g_Vl;

    const int tid = threadIdx.x;
    const int warp = tid >> 5, lane = tid & 31;
    const int q = lane >> 2, r = lane & 3;
    const int wm = warp & 3, wn = warp >> 2;
    const int m0 = blockIdx.y * 128, n0 = blockIdx.x * 128;

    float c[2][8][4];
#pragma unroll
    for (int mf = 0; mf < 2; ++mf)
#pragma unroll
        for (int nc = 0; nc < 8; ++nc)
#pragma unroll
            for (int i = 0; i < 4; ++i) c[mf][nc][i] = 0.f;

    auto stage = [&](int buf, int k0) {
        char* base = smG + buf * G_STAGE;
#pragma unroll
        for (int l = tid; l < 2048; l += 256) {
            int arr = l >> 9, idx = l & 511;
            int rr = idx >> 2, ch = idx & 3;
            const __nv_bfloat16* src;
            size_t off;
            if (arr < 2) {
                src = (arr == 0) ? g_Xh : g_Xl;
                off = (size_t)(m0 + rr) * 1024 + k0 + ch * 8;
            } else {
                src = (arr == 2) ? Bh : Bl;
                off = (size_t)(n0 + rr) * 1024 + k0 + ch * 8;
            }
            uint32_t dst = smem_addr_u32(base + arr * G_ARR + rr * G_STRIDE + ch * 16);
            CP_ASYNC16(dst, src + off);
        }
    };

    stage(0, 0);
    CP_COMMIT();

    for (int kt = 0; kt < 32; ++kt) {
        if (kt + 1 < 32) {
            stage((kt + 1) & 1, (kt + 1) * 32);
            CP_COMMIT();
            CP_WAIT(1);
        } else {
            CP_WAIT(0);
        }
        __syncthreads();

        char* base = smG + (kt & 1) * G_STAGE;
        char* Ah = base;
        char* Al = base + G_ARR;
        char* Bsh = base + 2 * G_ARR;
        char* Bsl = base + 3 * G_ARR;

#pragma unroll
        for (int k16 = 0; k16 < 2; ++k16) {
            const int kb = k16 * 32 + r * 4;
            uint32_t ah[2][4], al[2][4];
#pragma unroll
            for (int mf = 0; mf < 2; ++mf) {
                int mrow = wm * 32 + mf * 16 + q;
                ah[mf][0] = *(uint32_t*)(Ah + mrow * G_STRIDE + kb);
                ah[mf][1] = *(uint32_t*)(Ah + (mrow + 8) * G_STRIDE + kb);
                ah[mf][2] = *(uint32_t*)(Ah + mrow * G_STRIDE + kb + 16);
                ah[mf][3] = *(uint32_t*)(Ah + (mrow + 8) * G_STRIDE + kb + 16);
                al[mf][0] = *(uint32_t*)(Al + mrow * G_STRIDE + kb);
                al[mf][1] = *(uint32_t*)(Al + (mrow + 8) * G_STRIDE + kb);
                al[mf][2] = *(uint32_t*)(Al + mrow * G_STRIDE + kb + 16);
                al[mf][3] = *(uint32_t*)(Al + (mrow + 8) * G_STRIDE + kb + 16);
            }
#pragma unroll
            for (int nc = 0; nc < 8; ++nc) {
                int nrow = wn * 64 + nc * 8 + q;
                uint32_t bh0 = *(uint32_t*)(Bsh + nrow * G_STRIDE + kb);
                uint32_t bh1 = *(uint32_t*)(Bsh + nrow * G_STRIDE + kb + 16);
                uint32_t bl0 = *(uint32_t*)(Bsl + nrow * G_STRIDE + kb);
                uint32_t bl1 = *(uint32_t*)(Bsl + nrow * G_STRIDE + kb + 16);
#pragma unroll
                for (int mf = 0; mf < 2; ++mf) {
                    mma16816bf(c[mf][nc], ah[mf], bh0, bh1);
                    mma16816bf(c[mf][nc], ah[mf], bl0, bl1);
                    mma16816bf(c[mf][nc], al[mf], bh0, bh1);
                }
            }
        }
        __syncthreads();
    }

    // epilogue: add bias, split to fp16 hi/lo (K has no lo consumer)
#pragma unroll
    for (int mf = 0; mf < 2; ++mf) {
        int row = m0 + wm * 32 + mf * 16 + q;
#pragma unroll
        for (int nc = 0; nc < 8; ++nc) {
            int col = n0 + wn * 64 + nc * 8 + r * 2;
            float b0 = bias[col], b1 = bias[col + 1];
            uint32_t h, l;
            split2h(c[mf][nc][0] + b0, c[mf][nc][1] + b1, h, l);
            *(uint32_t*)(Gh + (size_t)row * 1024 + col) = h;
            if (Gl) *(uint32_t*)(Gl + (size_t)row * 1024 + col) = l;
            split2h(c[mf][nc][2] + b0, c[mf][nc][3] + b1, h, l);
            *(uint32_t*)(Gh + (size_t)(row + 8) * 1024 + col) = h;
            if (Gl) *(uint32_t*)(Gl + (size_t)(row + 8) * 1024 + col) = l;
        }
    }
}

// ---------------------------------------------------------------------------
// Kernel 2: HMMA flash attention, fp16 datapath.
// S = q_fp16 * k_fp16 (single term); PV = 3-term fp16 split.
// ---------------------------------------------------------------------------
#define OFF_KH   0
#define OFF_VTH  9216
#define OFF_VTL  18432
#define OFF_AK   27648    /* fp16 [128][132] = 33792 */
#define OFF_BAND 61440    /* fp16 [128][136] stride 272 = 34816 */
#define OFF_MS   96256
#define ATT_SMEM 96512
#define OFF_WRVT 0        /* overlay after mainloop: [64][136] fp16 = 17408 */

__global__ __launch_bounds__(256, 2)
void attn_mma_kernel(const float* __restrict__ mask,
                     const float* __restrict__ Wrk,   // [64][129]
                     const float* __restrict__ Wrv,   // [129][64]
                     float* __restrict__ out)
{
    extern __shared__ __align__(16) char sm[];
    const int tid  = threadIdx.x;
    const int warp = tid >> 5, lane = tid & 31;
    const int tq = lane >> 2, tr = lane & 3;
    const int lr = warp * 16 + tq;
    const int i0 = blockIdx.x * 128, hc = blockIdx.y * 64;

    __half* AK = (__half*)(sm + OFF_AK);
    float* MS = (float*)(sm + OFF_MS);
    const uint32_t sb = smem_addr_u32(sm);
    const uint32_t loff = ((lane & 7) + ((lane >> 1) & 8)) * 144 + ((lane & 8) << 1);
    const uint32_t loff272 = ((lane & 7) + ((lane >> 1) & 8)) * 272 + ((lane & 8) << 1);

    // ---- stage WrkT (fp16) into [0, 18432): w 0..63 at 0, w 64..127 at 9216 ----
    for (int l = tid; l < 1024; l += 256) {
        int w = l >> 4, dg = (l & 15) << 2;
        __half2 p01 = __floats2half2_rn(Wrk[(dg + 0) * 129 + w],      Wrk[(dg + 1) * 129 + w]);
        __half2 p23 = __floats2half2_rn(Wrk[(dg + 2) * 129 + w],      Wrk[(dg + 3) * 129 + w]);
        __half2 q01 = __floats2half2_rn(Wrk[(dg + 0) * 129 + w + 64], Wrk[(dg + 1) * 129 + w + 64]);
        __half2 q23 = __floats2half2_rn(Wrk[(dg + 2) * 129 + w + 64], Wrk[(dg + 3) * 129 + w + 64]);
        uint2 A = {*(uint32_t*)&p01, *(uint32_t*)&p23};
        uint2 B = {*(uint32_t*)&q01, *(uint32_t*)&q23};
        *(uint2*)(sm + 0    + w * 144 + dg * 2) = A;
        *(uint2*)(sm + 9216 + w * 144 + dg * 2) = B;
    }
    for (int l = tid; l < 8704; l += 256) ((uint32_t*)(sm + OFF_BAND))[l] = 0;
    if (tid < 128) {
        float s = 0.f;
        const __half* qh_ = g_Qh + (size_t)(i0 + tid) * 1024 + hc;
        const __half* ql_ = g_Ql + (size_t)(i0 + tid) * 1024 + hc;
#pragma unroll 8
        for (int d = 0; d < 64; ++d) {
            float qv = __half2float(qh_[d]) + __half2float(ql_[d]);
            s += qv * Wrk[d * 129 + 128];
        }
        AK[tid * 132 + 128] = __float2half(s);
    }
    __syncthreads();

    // ---- Q hi fragments (fp16, single term for S) ----
    uint32_t qh[4][4];
#pragma unroll
    for (int kc = 0; kc < 4; ++kc) {
        size_t r0 = (size_t)(i0 + lr) * 1024 + hc + kc * 16 + tr * 2;
        size_t r1 = (size_t)(i0 + lr + 8) * 1024 + hc + kc * 16 + tr * 2;
        qh[kc][0] = *(const uint32_t*)(g_Qh + r0);
        qh[kc][1] = *(const uint32_t*)(g_Qh + r1);
        qh[kc][2] = *(const uint32_t*)(g_Qh + r0 + 8);
        qh[kc][3] = *(const uint32_t*)(g_Qh + r1 + 8);
    }

    // ---- ak = Q @ WrkT^T via ldmatrix (fp16) ----
#pragma unroll
    for (int half = 0; half < 2; ++half) {
        const uint32_t KO = sb + (half ? 9216 : 0);
#pragma unroll
        for (int g = 0; g < 4; ++g) {
            float ca[4] = {0.f, 0.f, 0.f, 0.f}, cb[4] = {0.f, 0.f, 0.f, 0.f};
#pragma unroll
            for (int kc = 0; kc < 4; ++kc) {
                uint32_t h0, h1, h2, h3;
                ldsm4(KO + g * 2304 + kc * 32 + loff, h0, h1, h2, h3);
                mma16816h(ca, qh[kc], h0, h1);
                mma16816h(cb, qh[kc], h2, h3);
            }
#pragma unroll
            for (int pp = 0; pp < 2; ++pp) {
                const float* cc = pp ? cb : ca;
                int w = half * 64 + (2 * g + pp) * 8 + tr * 2;
                AK[lr * 132 + w]           = __float2half(cc[0]);
                AK[lr * 132 + w + 1]       = __float2half(cc[1]);
                AK[(lr + 8) * 132 + w]     = __float2half(cc[2]);
                AK[(lr + 8) * 132 + w + 1] = __float2half(cc[3]);
            }
        }
    }
    __syncthreads();   // WrkT region dead -> safe for cp.async overwrite

    // ---- pipelined staging lambdas ----
    auto stageK = [&](int j0) {
#pragma unroll
        for (int l = tid; l < 512; l += 256) {
            int r = l >> 3, ch = l & 7;
            const __half* src = g_Kh + (size_t)(j0 + r) * 1024 + hc + ch * 8;
            uint32_t dst = smem_addr_u32(sm + OFF_KH + r * 144 + ch * 16);
            CP_ASYNC16(dst, src);
        }
        if (tid < 16) {
            uint32_t dst = smem_addr_u32(sm + OFF_MS + tid * 16);
            CP_ASYNC16(dst, mask + j0 + tid * 4);
        }
    };
    auto stageV = [&](int j0) {
#pragma unroll
        for (int l = tid; l < 1024; l += 256) {
            int arr = l >> 9, idx = l & 511;
            int d = idx >> 3, ch = idx & 7;
            const __half* src =
                (arr ? g_VTl : g_VTh) + (size_t)(hc + d) * 2048 + j0 + ch * 8;
            uint32_t dst = smem_addr_u32(sm + OFF_VTH + arr * 9216 + d * 144 + ch * 16);
            CP_ASYNC16(dst, src);
        }
    };

    stageK(0); CP_COMMIT();
    stageV(0); CP_COMMIT();

    float ctx[8][4];
#pragma unroll
    for (int nc = 0; nc < 8; ++nc)
#pragma unroll
        for (int qq = 0; qq < 4; ++qq) ctx[nc][qq] = 0.f;
    float rs0 = 0.f, rs1 = 0.f, pe0 = 0.f, pe1 = 0.f;

#pragma unroll 1
    for (int jt = 0; jt < 32; ++jt) {
        const int j0 = jt * 64;
        CP_WAIT(1);              // K(jt)+mask ready (V may be in flight)
        __syncthreads();

        // ---- S = Q K^T (single fp16 term) via ldmatrix ----
        float c[8][4];
#pragma unroll
        for (int nc = 0; nc < 8; ++nc)
#pragma unroll
            for (int qq = 0; qq < 4; ++qq) c[nc][qq] = 0.f;
#pragma unroll
        for (int kc = 0; kc < 4; ++kc) {
#pragma unroll
            for (int g = 0; g < 4; ++g) {
                uint32_t h0, h1, h2, h3;
                ldsm4(sb + OFF_KH + g * 2304 + kc * 32 + loff, h0, h1, h2, h3);
                mma16816h(c[2 * g],     qh[kc], h0, h1);
                mma16816h(c[2 * g + 1], qh[kc], h2, h3);
            }
        }
        // snapshot additive mask before MS buffer gets overwritten by prefetch
        float am0[8], am1[8];
#pragma unroll
        for (int nc = 0; nc < 8; ++nc) {
            am0[nc] = (1.0f - MS[nc * 8 + tr * 2])     * (-1.0e30f);
            am1[nc] = (1.0f - MS[nc * 8 + tr * 2 + 1]) * (-1.0e30f);
        }
        __syncthreads();         // K + MS dead
        if (jt + 1 < 32) { stageK(j0 + 64); CP_COMMIT(); }

        // ---- epilogue: bias + scale + mask + exp2; band scatter ----
        const int sb0 = j0 - i0 + 64;
        const bool doBand = (sb0 >= -63 && sb0 <= 255);
#pragma unroll
        for (int nc = 0; nc < 8; ++nc) {
#pragma unroll
            for (int idx = 0; idx < 4; ++idx) {
                int lrr = lr + ((idx >> 1) << 3);
                int col = nc * 8 + tr * 2 + (idx & 1);
                float s = c[nc][idx];
                int w = sb0 + col - lrr;
                if (doBand && w >= 0 && w <= 128)
                    s += __half2float(AK[lrr * 132 + w]);
                float am = (idx & 1) ? am1[nc] : am0[nc];
                float e = exp2f(fmaf(s, 0.18033688f, am));
                if (idx < 2) rs0 += e; else rs1 += e;
                if (doBand) {
                    if (w >= 0 && w < 128)
                        *(__half*)(sm + OFF_BAND + lrr * 272 + w * 2) = __float2half(e);
                    else if (w == 128) { if (idx < 2) pe0 = e; else pe1 = e; }
                }
                c[nc][idx] = e;
            }
        }

        // ---- repack P as fp16 A-fragments (hi/lo) ----
        uint32_t ph[4][4], pl[4][4];
#pragma unroll
        for (int kc = 0; kc < 4; ++kc) {
            split2h(c[2 * kc][0],     c[2 * kc][1],     ph[kc][0], pl[kc][0]);
            split2h(c[2 * kc][2],     c[2 * kc][3],     ph[kc][1], pl[kc][1]);
            split2h(c[2 * kc + 1][0], c[2 * kc + 1][1], ph[kc][2], pl[kc][2]);
            split2h(c[2 * kc + 1][2], c[2 * kc + 1][3], ph[kc][3], pl[kc][3]);
        }

        if (jt + 1 < 32) { CP_WAIT(1); } else { CP_WAIT(0); }   // V(jt) ready
        __syncthreads();

        // ---- ctx += P V (3-term fp16 split) via ldmatrix ----
#pragma unroll
        for (int kc = 0; kc < 4; ++kc) {
#pragma unroll
            for (int g = 0; g < 4; ++g) {
                uint32_t h0, h1, h2, h3, e0, e1, e2, e3;
                ldsm4(sb + OFF_VTH + g * 2304 + kc * 32 + loff, h0, h1, h2, h3);
                ldsm4(sb + OFF_VTL + g * 2304 + kc * 32 + loff, e0, e1, e2, e3);
                mma16816h(ctx[2 * g],     ph[kc], h0, h1);
                mma16816h(ctx[2 * g],     ph[kc], e0, e1);
                mma16816h(ctx[2 * g],     pl[kc], h0, h1);
                mma16816h(ctx[2 * g + 1], ph[kc], h2, h3);
                mma16816h(ctx[2 * g + 1], ph[kc], e2, e3);
                mma16816h(ctx[2 * g + 1], pl[kc], h2, h3);
            }
        }
        __syncthreads();         // V dead
        if (jt + 1 < 32) { stageV(j0 + 64); CP_COMMIT(); }
    }

    // ---- stage WrvT [d][136] (fp16), overlay on K/VT-hi region ----
    for (int l = tid; l < 8192; l += 256) {
        int d = l >> 7, w = l & 127;
        *(__half*)(sm + OFF_WRVT + d * 272 + w * 2) = __float2half(Wrv[w * 64 + d]);
    }
    __syncthreads();

    // ---- ctx += band @ WrvT^T (ldmatrix, 272B stride) ----
#pragma unroll
    for (int kc = 0; kc < 8; ++kc) {
        int cb = (kc * 16 + tr * 2) * 2;
        uint32_t af[4];
        af[0] = *(uint32_t*)(sm + OFF_BAND + lr * 272 + cb);
        af[1] = *(uint32_t*)(sm + OFF_BAND + (lr + 8) * 272 + cb);
        af[2] = *(uint32_t*)(sm + OFF_BAND + lr * 272 + cb + 16);
        af[3] = *(uint32_t*)(sm + OFF_BAND + (lr + 8) * 272 + cb + 16);
#pragma unroll
        for (int g = 0; g < 4; ++g) {
            uint32_t h0, h1, h2, h3;
            ldsm4(sb + OFF_WRVT + g * 16 * 272 + kc * 32 + loff272, h0, h1, h2, h3);
            mma16816h(ctx[2 * g],     af, h0, h1);
            mma16816h(ctx[2 * g + 1], af, h2, h3);
        }
    }

    // ---- reduce rowsums / edge-p across the quad, write out ----
    rs0 += __shfl_xor_sync(0xffffffffu, rs0, 1);
    rs0 += __shfl_xor_sync(0xffffffffu, rs0, 2);
    rs1 += __shfl_xor_sync(0xffffffffu, rs1, 1);
    rs1 += __shfl_xor_sync(0xffffffffu, rs1, 2);
    pe0 += __shfl_xor_sync(0xffffffffu, pe0, 1);
    pe0 += __shfl_xor_sync(0xffffffffu, pe0, 2);
    pe1 += __shfl_xor_sync(0xffffffffu, pe1, 1);
    pe1 += __shfl_xor_sync(0xffffffffu, pe1, 2);
    float inv0 = 1.0f / rs0, inv1 = 1.0f / rs1;
    const float* wrvE = Wrv + 128 * 64;
#pragma unroll
    for (int nc = 0; nc < 8; ++nc) {
        int d = nc * 8 + tr * 2;
        float2 o0, o1;
        o0.x = (ctx[nc][0] + pe0 * wrvE[d])     * inv0;
        o0.y = (ctx[nc][1] + pe0 * wrvE[d + 1]) * inv0;
        o1.x = (ctx[nc][2] + pe1 * wrvE[d])     * inv1;
        o1.y = (ctx[nc][3] + pe1 * wrvE[d + 1]) * inv1;
        *(float2*)(out + (size_t)(i0 + lr) * 1024 + hc + d)     = o0;
        *(float2*)(out + (size_t)(i0 + lr + 8) * 1024 + hc + d) = o1;
    }
}

// ---------------------------------------------------------------------------
extern "C" void kernel_launch(void* const* d_in, const int* in_sizes, int n_in,
                              void* d_out, int out_size)
{
    const float* X   = (const float*)d_in[0];
    const float* msk = (const float*)d_in[1];
    const float* Wq  = (const float*)d_in[2];
    const float* bq  = (const float*)d_in[3];
    const float* Wk  = (const float*)d_in[4];
    const float* bk  = (const float*)d_in[5];
    const float* Wv  = (const float*)d_in[6];
    const float* bv  = (const float*)d_in[7];
    const float* Wrk = (const float*)d_in[8];
    const float* Wrv = (const float*)d_in[9];
    float* out = (float*)d_out;

    cudaFuncSetAttribute(qkv_hmma_kernel,
                         cudaFuncAttributeMaxDynamicSharedMemorySize, GEMM_SMEM);
    cudaFuncSetAttribute(attn_mma_kernel,
                         cudaFuncAttributeMaxDynamicSharedMemorySize, ATT_SMEM);

    convert_x_kernel<<<2048, 256>>>(X);
    convert_w_kernel<<<dim3(32, 32, 3), dim3(32, 8)>>>(Wq, Wk, Wv);
    qkv_hmma_kernel<<<dim3(8, 16, 3), 256, GEMM_SMEM>>>(bq, bk, bv);
    transpose_v_kernel<<<dim3(64, 32, 2), dim3(32, 8)>>>();

    dim3 gAttn(16, 16);
    attn_mma_kernel<<<gAttn, 256, ATT_SMEM>>>(msk, Wrk, Wrv, out);
}